// round 13
// baseline (speedup 1.0000x reference)
#include <cuda_runtime.h>
#include <cuda_bf16.h>
#include <cstdint>

// ---------------- problem constants ----------------
#define MB   4
#define SEQ  2048
#define EMB  512
#define NH   8
#define HD   64
#define FF   2048
#define ROWS (MB*SEQ)     // 8192
#define BHN  (MB*NH)      // 32
#define QKVN (3*EMB)      // 1536

// ---------------- scratch (device globals) ----------------
__device__ __nv_bfloat16 g_n1bf[(size_t)ROWS*EMB];
__device__ __nv_bfloat16 g_n2bf[(size_t)ROWS*EMB];
__device__ __nv_bfloat16 g_wqkvt[(size_t)QKVN*EMB];   // [N=1536, K=512] bf16
__device__ __nv_bfloat16 g_w1t[(size_t)FF*EMB];       // [N=2048, K=512] bf16
__device__ float    g_bqkv[QKVN];
__device__ float    g_qkv[(size_t)ROWS*QKVN];         // [8192, 1536] q|k (v region unused)
__device__ __nv_bfloat16 g_vbf[(size_t)BHN*SEQ*HD];   // [bh][seq][64] bf16
__device__ float    g_ctx[(size_t)ROWS*EMB];
__device__ uint32_t g_bits[(size_t)ROWS*(FF/32)];

// ---------------- helpers ----------------
static __device__ __forceinline__ uint32_t s2u(const void* p) {
    uint32_t a;
    asm("{ .reg .u64 t; cvta.to.shared.u64 t, %1; cvt.u32.u64 %0, t; }" : "=r"(a) : "l"(p));
    return a;
}
static __device__ __forceinline__ void cp16(uint32_t s, const void* g) {
    asm volatile("cp.async.ca.shared.global [%0], [%1], 16;"
                 :: "r"(s), "l"(__cvta_generic_to_global(g)) : "memory");
}
static __device__ __forceinline__ void ldm_x4(uint32_t addr, uint32_t& r0, uint32_t& r1,
                                              uint32_t& r2, uint32_t& r3) {
    asm volatile("ldmatrix.sync.aligned.m8n8.x4.shared.b16 {%0,%1,%2,%3}, [%4];"
                 : "=r"(r0), "=r"(r1), "=r"(r2), "=r"(r3) : "r"(addr));
}
static __device__ __forceinline__ void ldm_x4t(uint32_t addr, uint32_t& r0, uint32_t& r1,
                                               uint32_t& r2, uint32_t& r3) {
    asm volatile("ldmatrix.sync.aligned.m8n8.x4.trans.shared.b16 {%0,%1,%2,%3}, [%4];"
                 : "=r"(r0), "=r"(r1), "=r"(r2), "=r"(r3) : "r"(addr));
}
static __device__ __forceinline__ void mma16816(float* d, const uint32_t* a,
                                                uint32_t b0, uint32_t b1) {
    asm volatile("mma.sync.aligned.m16n8k16.row.col.f32.bf16.bf16.f32 "
                 "{%0,%1,%2,%3}, {%4,%5,%6,%7}, {%8,%9}, {%0,%1,%2,%3};"
                 : "+f"(d[0]), "+f"(d[1]), "+f"(d[2]), "+f"(d[3])
                 : "r"(a[0]), "r"(a[1]), "r"(a[2]), "r"(a[3]), "r"(b0), "r"(b1));
}
static __device__ __forceinline__ void mma_tf32(float* d, const uint32_t* a,
                                                uint32_t b0, uint32_t b1) {
    asm volatile("mma.sync.aligned.m16n8k8.row.col.f32.tf32.tf32.f32 "
                 "{%0,%1,%2,%3}, {%4,%5,%6,%7}, {%8,%9}, {%0,%1,%2,%3};"
                 : "+f"(d[0]), "+f"(d[1]), "+f"(d[2]), "+f"(d[3])
                 : "r"(a[0]), "r"(a[1]), "r"(a[2]), "r"(a[3]), "r"(b0), "r"(b1));
}
static __device__ __forceinline__ float f2tf32(float v) {
    uint32_t u;
    asm("cvt.rna.tf32.f32 %0, %1;" : "=r"(u) : "f"(v));
    return __uint_as_float(u);
}
static __device__ __forceinline__ uint32_t packbf2(float x, float y) {
    __nv_bfloat162 h = __floats2bfloat162_rn(x, y);
    return *(uint32_t*)&h;
}

// ---------------- block reduce (128 threads) ----------------
__device__ __forceinline__ void blockReduce2_128(float &a, float &b) {
    #pragma unroll
    for (int off = 16; off; off >>= 1) {
        a += __shfl_xor_sync(0xffffffffu, a, off);
        b += __shfl_xor_sync(0xffffffffu, b, off);
    }
    __shared__ float sa[4], sb[4];
    int w = threadIdx.x >> 5, ln = threadIdx.x & 31;
    if (ln == 0) { sa[w] = a; sb[w] = b; }
    __syncthreads();
    a = sa[0] + sa[1] + sa[2] + sa[3];
    b = sb[0] + sb[1] + sb[2] + sb[3];
}

static __device__ __forceinline__ void st_bf4(__nv_bfloat16* p, float4 o) {
    __nv_bfloat162 a = __floats2bfloat162_rn(o.x, o.y);
    __nv_bfloat162 b = __floats2bfloat162_rn(o.z, o.w);
    uint2 u;
    u.x = *(uint32_t*)&a;
    u.y = *(uint32_t*)&b;
    *(uint2*)p = u;
}

// ---------------- LN1 ----------------
__global__ void ln_kernel(const float* __restrict__ x,
                          const float* __restrict__ gam,
                          const float* __restrict__ bet,
                          __nv_bfloat16* __restrict__ out)
{
    int row = blockIdx.x;
    int t = threadIdx.x;
    float4 v = ((const float4*)(x + (size_t)row * EMB))[t];
    float s  = v.x + v.y + v.z + v.w;
    float ss = v.x*v.x + v.y*v.y + v.z*v.z + v.w*v.w;
    blockReduce2_128(s, ss);
    float mean = s * (1.0f / EMB);
    float var  = ss * (1.0f / EMB) - mean * mean;
    float r = rsqrtf(var + 1e-5f);
    float4 gv = ((const float4*)gam)[t];
    float4 bv = ((const float4*)bet)[t];
    float4 o;
    o.x = (v.x - mean) * r * gv.x + bv.x;
    o.y = (v.y - mean) * r * gv.y + bv.y;
    o.z = (v.z - mean) * r * gv.z + bv.z;
    o.w = (v.w - mean) * r * gv.w + bv.w;
    st_bf4(out + (size_t)row * EMB + t * 4, o);
}

// ---------------- residual add + LN2 ----------------
__global__ void add_ln_kernel(const float* __restrict__ x,
                              const float* __restrict__ ctx,
                              const float* __restrict__ gam,
                              const float* __restrict__ bet,
                              float* __restrict__ x1out,
                              __nv_bfloat16* __restrict__ nout)
{
    int row = blockIdx.x;
    int t = threadIdx.x;
    float4 xv = ((const float4*)(x   + (size_t)row * EMB))[t];
    float4 cv = ((const float4*)(ctx + (size_t)row * EMB))[t];
    float4 v;
    v.x = xv.x + cv.x; v.y = xv.y + cv.y; v.z = xv.z + cv.z; v.w = xv.w + cv.w;
    ((float4*)(x1out + (size_t)row * EMB))[t] = v;

    float s  = v.x + v.y + v.z + v.w;
    float ss = v.x*v.x + v.y*v.y + v.z*v.z + v.w*v.w;
    blockReduce2_128(s, ss);
    float mean = s * (1.0f / EMB);
    float var  = ss * (1.0f / EMB) - mean * mean;
    float r = rsqrtf(var + 1e-5f);
    float4 gv = ((const float4*)gam)[t];
    float4 bv = ((const float4*)bet)[t];
    float4 o;
    o.x = (v.x - mean) * r * gv.x + bv.x;
    o.y = (v.y - mean) * r * gv.y + bv.y;
    o.z = (v.z - mean) * r * gv.z + bv.z;
    o.w = (v.w - mean) * r * gv.w + bv.w;
    st_bf4(nout + (size_t)row * EMB + t * 4, o);
}

// ---------------- fused weight transposes: f32 [K,N] -> bf16 [N,K] ----------------
__global__ void transpose_all(const float* __restrict__ wq, const float* __restrict__ wk,
                              const float* __restrict__ wv, const float* __restrict__ w1,
                              __nv_bfloat16* __restrict__ wqkvt, __nv_bfloat16* __restrict__ w1t)
{
    __shared__ float tile[32][33];
    int bx = blockIdx.x;
    const float* in;
    __nv_bfloat16* out;
    int N, nb;
    if (bx < 48) {
        int mi = bx >> 4;
        in = (mi == 0) ? wq : ((mi == 1) ? wk : wv);
        out = wqkvt + (size_t)mi * 512 * EMB;
        N = 512;
        nb = (bx & 15) * 32;
    } else {
        in = w1; out = w1t; N = FF; nb = (bx - 48) * 32;
    }
    int kb = blockIdx.y * 32;
    int tx = threadIdx.x, ty = threadIdx.y;   // 32 x 8
    #pragma unroll
    for (int i = 0; i < 32; i += 8)
        tile[ty + i][tx] = in[(size_t)(kb + ty + i) * N + nb + tx];
    __syncthreads();
    #pragma unroll
    for (int i = 0; i < 32; i += 8)
        out[(size_t)(nb + ty + i) * EMB + kb + tx] = __float2bfloat16_rn(tile[tx][ty + i]);
}

__global__ void combine_bias(const float* __restrict__ bq, const float* __restrict__ bk,
                             const float* __restrict__ bv, float* __restrict__ o)
{
    int i = blockIdx.x * 256 + threadIdx.x;
    if (i < QKVN)
        o[i] = (i < 512) ? bq[i] : ((i < 1024) ? bk[i - 512] : bv[i - 1024]);
}

// exact fp32 recompute of h1[row][col] (rare borderline path)
static __device__ float exact_h1(const float* __restrict__ x1row,
                                 const float* __restrict__ g2,
                                 const float* __restrict__ be2,
                                 const float* __restrict__ w1f,
                                 int col, float bias0)
{
    float s = 0.f, ss = 0.f;
    for (int k = 0; k < EMB; ++k) { float v = x1row[k]; s += v; ss += v * v; }
    float mu = s * (1.0f / EMB);
    float var = ss * (1.0f / EMB) - mu * mu;
    float r = rsqrtf(var + 1e-5f);
    float d = bias0;
    for (int k = 0; k < EMB; ++k) {
        float nv = (x1row[k] - mu) * r * g2[k] + be2[k];
        d += nv * w1f[(size_t)k * FF + col];
    }
    return d;
}

// ---------------- HMMA bf16 GEMM ----------------
// EPI 0 (QKV): q,k -> tf32-rounded fp32 in C; v -> bf16 in vbf[bh][seq][64]
// EPI 1 (FFN1): spike bitmask, borderline re-verified via exact fp32 LN+dot.
#define KCH 32
#define LDHW 40
#define STGH (128*LDHW)

template<int EPI>
__global__ void __launch_bounds__(256)
hmma_gemm(const __nv_bfloat16* __restrict__ A, const __nv_bfloat16* __restrict__ Bt,
          const float* __restrict__ bias, float* __restrict__ C,
          uint32_t* __restrict__ bits, int ldC,
          const float* __restrict__ x1, const float* __restrict__ g2,
          const float* __restrict__ be2, const float* __restrict__ w1f,
          __nv_bfloat16* __restrict__ vbf)
{
    __shared__ __align__(16) __nv_bfloat16 sA[2][STGH];
    __shared__ __align__(16) __nv_bfloat16 sB[2][STGH];
    __shared__ float sBias[128];

    int t = threadIdx.x, lane = t & 31, warp = t >> 5;
    int wm = warp >> 2;
    int wn = warp & 3;
    int m0 = blockIdx.y * 128, n0 = blockIdx.x * 128;

    if (t < 128) sBias[t] = bias[n0 + t];

    uint32_t sAu = s2u(&sA[0][0]);
    uint32_t sBu = s2u(&sB[0][0]);
    int lr0 = t >> 2, lc = (t & 3) * 8;

    {
        #pragma unroll
        for (int it = 0; it < 2; ++it) {
            int r = lr0 + it * 64;
            uint32_t off = (uint32_t)(r * LDHW + lc) * 2;
            cp16(sAu + off, A  + (size_t)(m0 + r) * EMB + lc);
            cp16(sBu + off, Bt + (size_t)(n0 + r) * EMB + lc);
        }
        asm volatile("cp.async.commit_group;" ::: "memory");
    }

    float acc[4][4][4];
    #pragma unroll
    for (int i = 0; i < 4; i++)
        #pragma unroll
        for (int j = 0; j < 4; j++)
            #pragma unroll
            for (int f = 0; f < 4; f++) acc[i][j][f] = 0.f;

    const int NSTEP = EMB / KCH;
    #pragma unroll 1
    for (int s = 0; s < NSTEP; ++s) {
        if (s + 1 < NSTEP) {
            int stg = (s + 1) & 1;
            #pragma unroll
            for (int it = 0; it < 2; ++it) {
                int r = lr0 + it * 64;
                uint32_t off = (uint32_t)(stg * STGH + r * LDHW + lc) * 2;
                cp16(sAu + off, A  + (size_t)(m0 + r) * EMB + (s + 1) * KCH + lc);
                cp16(sBu + off, Bt + (size_t)(n0 + r) * EMB + (s + 1) * KCH + lc);
            }
            asm volatile("cp.async.commit_group;" ::: "memory");
            asm volatile("cp.async.wait_group 1;" ::: "memory");
        } else {
            asm volatile("cp.async.wait_group 0;" ::: "memory");
        }
        __syncthreads();

        int stg = s & 1;
        uint32_t aB = sAu + (uint32_t)(stg * STGH) * 2;
        uint32_t bB = sBu + (uint32_t)(stg * STGH) * 2;

        #pragma unroll
        for (int k16 = 0; k16 < 2; ++k16) {
            uint32_t a[4][4];
            #pragma unroll
            for (int mt = 0; mt < 4; ++mt) {
                int row = wm * 64 + mt * 16 + (lane & 15);
                int col = k16 * 16 + (lane >> 4) * 8;
                ldm_x4(aB + (uint32_t)(row * LDHW + col) * 2,
                       a[mt][0], a[mt][1], a[mt][2], a[mt][3]);
            }
            uint32_t b[2][4];
            #pragma unroll
            for (int nb = 0; nb < 2; ++nb) {
                int nrow = wn * 32 + nb * 16 + (lane & 7) + ((lane >> 4) & 1) * 8;
                int col  = k16 * 16 + ((lane >> 3) & 1) * 8;
                ldm_x4(bB + (uint32_t)(nrow * LDHW + col) * 2,
                       b[nb][0], b[nb][1], b[nb][2], b[nb][3]);
            }
            #pragma unroll
            for (int mt = 0; mt < 4; ++mt)
                #pragma unroll
                for (int nt = 0; nt < 4; ++nt)
                    mma16816(acc[mt][nt], a[mt],
                             b[nt >> 1][(nt & 1) * 2], b[nt >> 1][(nt & 1) * 2 + 1]);
        }
        __syncthreads();
    }

    int qr = lane >> 2;
    int qc = (lane & 3) * 2;
    if (EPI == 0) {
        #pragma unroll
        for (int mt = 0; mt < 4; ++mt) {
            int r0 = m0 + wm * 64 + mt * 16 + qr;
            #pragma unroll
            for (int nt = 0; nt < 4; ++nt) {
                int cofs = wn * 32 + nt * 8 + qc;
                int col = n0 + cofs;
                float v00 = acc[mt][nt][0] + sBias[cofs];
                float v01 = acc[mt][nt][1] + sBias[cofs + 1];
                float v10 = acc[mt][nt][2] + sBias[cofs];
                float v11 = acc[mt][nt][3] + sBias[cofs + 1];
                if (col < 1024) {
                    // q/k: pre-round to tf32 so attention HW truncation is exact
                    float2 a2, b2;
                    a2.x = f2tf32(v00); a2.y = f2tf32(v01);
                    b2.x = f2tf32(v10); b2.y = f2tf32(v11);
                    *(float2*)(C + (size_t)r0 * ldC + col)       = a2;
                    *(float2*)(C + (size_t)(r0 + 8) * ldC + col) = b2;
                } else {
                    int hh = (col - 1024) >> 6, dd = (col - 1024) & 63;
                    size_t i0 = ((((size_t)(r0 >> 11)) * NH + hh) * SEQ + (r0 & (SEQ - 1))) * HD + dd;
                    size_t i1 = ((((size_t)(r0 >> 11)) * NH + hh) * SEQ + ((r0 + 8) & (SEQ - 1))) * HD + dd;
                    *(uint32_t*)(vbf + i0) = packbf2(v00, v01);
                    *(uint32_t*)(vbf + i1) = packbf2(v10, v11);
                }
            }
        }
    } else {
        #pragma unroll
        for (int mt = 0; mt < 4; ++mt) {
            int r0 = m0 + wm * 64 + mt * 16 + qr;
            uint32_t w0 = 0, w1m = 0;
            #pragma unroll
            for (int nt = 0; nt < 4; ++nt) {
                int cofs = wn * 32 + nt * 8 + qc;
                int col = n0 + cofs;
                #pragma unroll
                for (int e = 0; e < 2; ++e) {
                    int pos = nt * 8 + qc + e;
                    float b0 = sBias[cofs + e];
                    float va = acc[mt][nt][e] + b0;
                    float vb = acc[mt][nt][2 + e] + b0;
                    if (fabsf(va - 2.0f) < 0.02f)
                        va = exact_h1(x1 + (size_t)r0 * EMB, g2, be2, w1f, col + e, b0);
                    if (fabsf(vb - 2.0f) < 0.02f)
                        vb = exact_h1(x1 + (size_t)(r0 + 8) * EMB, g2, be2, w1f, col + e, b0);
                    if (va >= 2.0f) w0  |= (1u << pos);
                    if (vb >= 2.0f) w1m |= (1u << pos);
                }
            }
            w0  |= __shfl_xor_sync(0xffffffffu, w0, 1);
            w0  |= __shfl_xor_sync(0xffffffffu, w0, 2);
            w1m |= __shfl_xor_sync(0xffffffffu, w1m, 1);
            w1m |= __shfl_xor_sync(0xffffffffu, w1m, 2);
            if ((lane & 3) == 0) {
                int wcol = (n0 >> 5) + wn;
                bits[(size_t)r0 * (FF/32) + wcol]       = w0;
                bits[(size_t)(r0 + 8) * (FF/32) + wcol] = w1m;
            }
        }
    }
}

// ---------------- tensor-core flash attention (round-4 structure, verbatim) ----------------
// CTA: 64 q rows of one (m,h); 4 warps x 16 rows; 64-key tiles double-buffered.
// QK^T in tf32 (q,k pre-rounded), online softmax fp32 (__expf), P*V in bf16.
// smem: Q f32 [64][68] | K f32 [2][64][68] | V bf16 [2][64][72]
#define ASM_Q 0
#define ASM_K 17408
#define ASM_V 52224
#define ATT_SMEM 70656

__global__ void __launch_bounds__(128, 3)
attn_tc(const float* __restrict__ qkv, const __nv_bfloat16* __restrict__ vbf,
        float* __restrict__ O)
{
    extern __shared__ __align__(16) char smx[];
    float* Qs = (float*)(smx + ASM_Q);
    uint32_t smb = s2u(smx);

    int bh = blockIdx.y;
    int m = bh >> 3, h = bh & 7;
    int q0 = blockIdx.x * 64;
    int t = threadIdx.x, lane = t & 31, warp = t >> 5;
    int g = lane >> 2, tq = lane & 3;

    const float* qg = qkv + ((size_t)(m * SEQ + q0)) * QKVN + h * 64;
    const float* kg0 = qkv + ((size_t)m * SEQ) * QKVN + 512 + h * 64;
    const __nv_bfloat16* vg0 = vbf + ((size_t)bh * SEQ) * HD;

    // prefetch tile 0 (K fp32 + V bf16)
    {
        #pragma unroll
        for (int i = 0; i < 8; ++i) {
            int idx = t + i * 128;
            int r = idx >> 4, c = idx & 15;
            cp16(smb + ASM_K + r * 272 + c * 16, kg0 + (size_t)r * QKVN + c * 4);
        }
        #pragma unroll
        for (int i = 0; i < 4; ++i) {
            int idx = t + i * 128;
            int r = idx >> 3, c = idx & 7;
            cp16(smb + ASM_V + r * 144 + c * 16, vg0 + (size_t)r * HD + c * 8);
        }
        asm volatile("cp.async.commit_group;" ::: "memory");
    }

    // stage Q and build tf32 A-fragments (kept in regs for all tiles)
    #pragma unroll
    for (int i = 0; i < 8; ++i) {
        int idx = t + i * 128;
        int r = idx >> 4, c = (idx & 15) * 4;
        *(float4*)&Qs[r * 68 + c] = *(const float4*)(qg + (size_t)r * QKVN + c);
    }
    __syncthreads();
    uint32_t qf[8][4];
    {
        int qrow = warp * 16 + g;
        #pragma unroll
        for (int s = 0; s < 8; ++s) {
            qf[s][0] = __float_as_uint(Qs[qrow * 68 + s * 8 + tq]);
            qf[s][1] = __float_as_uint(Qs[(qrow + 8) * 68 + s * 8 + tq]);
            qf[s][2] = __float_as_uint(Qs[qrow * 68 + s * 8 + tq + 4]);
            qf[s][3] = __float_as_uint(Qs[(qrow + 8) * 68 + s * 8 + tq + 4]);
        }
    }

    float mrow[2] = {-1e30f, -1e30f}, lrow[2] = {0.f, 0.f};
    float accO[8][4];
    #pragma unroll
    for (int j = 0; j < 8; ++j)
        #pragma unroll
        for (int e = 0; e < 4; ++e) accO[j][e] = 0.f;

    #pragma unroll 1
    for (int kt = 0; kt < SEQ / 64; ++kt) {
        __syncthreads();   // all warps done with the stage about to be overwritten
        if (kt + 1 < SEQ / 64) {
            int st = (kt + 1) & 1;
            const float* kg = kg0 + (size_t)(kt + 1) * 64 * QKVN;
            const __nv_bfloat16* vg = vg0 + (size_t)(kt + 1) * 64 * HD;
            #pragma unroll
            for (int i = 0; i < 8; ++i) {
                int idx = t + i * 128;
                int r = idx >> 4, c = idx & 15;
                cp16(smb + ASM_K + st * 17408 + r * 272 + c * 16, kg + (size_t)r * QKVN + c * 4);
            }
            #pragma unroll
            for (int i = 0; i < 4; ++i) {
                int idx = t + i * 128;
                int r = idx >> 3, c = idx & 7;
                cp16(smb + ASM_V + st * 9216 + r * 144 + c * 16, vg + (size_t)r * HD + c * 8);
            }
            asm volatile("cp.async.commit_group;" ::: "memory");
            asm volatile("cp.async.wait_group 1;" ::: "memory");
        } else {
            asm volatile("cp.async.wait_group 0;" ::: "memory");
        }
        __syncthreads();

        int st = kt & 1;
        const float* Ks = (const float*)(smx + ASM_K + st * 17408);

        // ---- S = Q K^T (tf32) ----
        float accS[8][4];
        #pragma unroll
        for (int j = 0; j < 8; ++j)
            #pragma unroll
            for (int e = 0; e < 4; ++e) accS[j][e] = 0.f;

        #pragma unroll
        for (int s = 0; s < 8; ++s) {
            #pragma unroll
            for (int j = 0; j < 8; ++j) {
                uint32_t b0 = __float_as_uint(Ks[(j * 8 + g) * 68 + s * 8 + tq]);
                uint32_t b1 = __float_as_uint(Ks[(j * 8 + g) * 68 + s * 8 + tq + 4]);
                mma_tf32(accS[j], qf[s], b0, b1);
            }
        }

        // ---- online softmax (rows g, g+8 of this warp's 16) ----
        float mx0 = -1e30f, mx1 = -1e30f;
        #pragma unroll
        for (int j = 0; j < 8; ++j) {
            mx0 = fmaxf(mx0, fmaxf(accS[j][0], accS[j][1]));
            mx1 = fmaxf(mx1, fmaxf(accS[j][2], accS[j][3]));
        }
        mx0 = fmaxf(mx0, __shfl_xor_sync(0xffffffffu, mx0, 1));
        mx0 = fmaxf(mx0, __shfl_xor_sync(0xffffffffu, mx0, 2));
        mx1 = fmaxf(mx1, __shfl_xor_sync(0xffffffffu, mx1, 1));
        mx1 = fmaxf(mx1, __shfl_xor_sync(0xffffffffu, mx1, 2));
        float mn0 = fmaxf(mrow[0], mx0), mn1 = fmaxf(mrow[1], mx1);
        float sc0 = __expf(mrow[0] - mn0), sc1 = __expf(mrow[1] - mn1);
        float sum0 = 0.f, sum1 = 0.f;
        #pragma unroll
        for (int j = 0; j < 8; ++j) {
            accS[j][0] = __expf(accS[j][0] - mn0);
            accS[j][1] = __expf(accS[j][1] - mn0);
            accS[j][2] = __expf(accS[j][2] - mn1);
            accS[j][3] = __expf(accS[j][3] - mn1);
            sum0 += accS[j][0] + accS[j][1];
            sum1 += accS[j][2] + accS[j][3];
        }
        sum0 += __shfl_xor_sync(0xffffffffu, sum0, 1);
        sum0 += __shfl_xor_sync(0xffffffffu, sum0, 2);
        sum1 += __shfl_xor_sync(0xffffffffu, sum1, 1);
        sum1 += __shfl_xor_sync(0xffffffffu, sum1, 2);
        lrow[0] = lrow[0] * sc0 + sum0;
        lrow[1] = lrow[1] * sc1 + sum1;
        mrow[0] = mn0; mrow[1] = mn1;
        #pragma unroll
        for (int j = 0; j < 8; ++j) {
            accO[j][0] *= sc0; accO[j][1] *= sc0;
            accO[j][2] *= sc1; accO[j][3] *= sc1;
        }

        // ---- O += P V (bf16); P fragments come straight from accS ----
        uint32_t vB = smb + ASM_V + st * 9216;
        #pragma unroll
        for (int sk = 0; sk < 4; ++sk) {
            uint32_t pa[4];
            pa[0] = packbf2(accS[2 * sk][0],     accS[2 * sk][1]);
            pa[1] = packbf2(accS[2 * sk][2],     accS[2 * sk][3]);
            pa[2] = packbf2(accS[2 * sk + 1][0], accS[2 * sk + 1][1]);
            pa[3] = packbf2(accS[2 * sk + 1][2], accS[2 * sk + 1][3]);
            #pragma unroll
            for (int dj = 0; dj < 4; ++dj) {
                uint32_t v0, v1, v2, v3;
                uint32_t addr = vB + (uint32_t)((sk * 16 + (lane & 15)) * 144
                              + (dj * 16 + 8 * (lane >> 4)) * 2);
                ldm_x4t(addr, v0, v1, v2, v3);
                mma16816(accO[2 * dj],     pa, v0, v1);
                mma16816(accO[2 * dj + 1], pa, v2, v3);
            }
        }
    }

    // ---- epilogue ----
    float inv0 = 1.0f / lrow[0];
    float inv1 = 1.0f / lrow[1];
    int qrow = warp * 16 + g;
    float* ob = O + ((size_t)(m * SEQ + q0 + qrow)) * EMB + h * 64;
    #pragma unroll
    for (int j = 0; j < 8; ++j) {
        float2 a2, b2;
        a2.x = accO[j][0] * inv0; a2.y = accO[j][1] * inv0;
        b2.x = accO[j][2] * inv1; b2.y = accO[j][3] * inv1;
        *(float2*)(ob + j * 8 + 2 * tq) = a2;
        *(float2*)(ob + (size_t)8 * EMB + j * 8 + 2 * tq) = b2;
    }
}

// ---------------- sparse FFN2 ----------------
__global__ void __launch_bounds__(128)
ffn2_sparse(const uint32_t* __restrict__ bits, const float* __restrict__ w2,
            const float* __restrict__ b2, float* __restrict__ out)
{
    int row = blockIdx.x, t = threadIdx.x;
    __shared__ uint32_t sm[FF/32];
    if (t < FF/32) sm[t] = bits[(size_t)row * (FF/32) + t];
    __syncthreads();
    float4 acc = *(const float4*)(b2 + t * 4);
    #pragma unroll 4
    for (int w = 0; w < FF/32; ++w) {
        uint32_t m = sm[w];
        while (m) {
            int j = __ffs((int)m) - 1;
            m &= m - 1;
            int col = w * 32 + j;
            float4 wv = *(const float4*)(w2 + (size_t)col * EMB + t * 4);
            acc.x += wv.x; acc.y += wv.y; acc.z += wv.z; acc.w += wv.w;
        }
    }
    float4 cur = *(const float4*)(out + (size_t)row * EMB + t * 4);
    cur.x += acc.x; cur.y += acc.y; cur.z += acc.z; cur.w += acc.w;
    *(float4*)(out + (size_t)row * EMB + t * 4) = cur;
}

// ---------------- launch ----------------
extern "C" void kernel_launch(void* const* d_in, const int* in_sizes, int n_in,
                              void* d_out, int out_size)
{
    const float* x   = (const float*)d_in[0];
    const float* wq  = (const float*)d_in[1];
    const float* bq  = (const float*)d_in[2];
    const float* wk  = (const float*)d_in[3];
    const float* bk  = (const float*)d_in[4];
    const float* wv  = (const float*)d_in[5];
    const float* bv  = (const float*)d_in[6];
    const float* w1  = (const float*)d_in[7];
    const float* b1  = (const float*)d_in[8];
    const float* w2  = (const float*)d_in[9];
    const float* b2  = (const float*)d_in[10];
    const float* gm1 = (const float*)d_in[11];
    const float* be1 = (const float*)d_in[12];
    const float* gm2 = (const float*)d_in[13];
    const float* be2 = (const float*)d_in[14];
    float* out = (float*)d_out;

    __nv_bfloat16 *n1bf, *n2bf, *wqkvt, *w1t, *vbf;
    float *bqkv, *qkv, *ctx;
    uint32_t *bits;
    cudaGetSymbolAddress((void**)&n1bf,  g_n1bf);
    cudaGetSymbolAddress((void**)&n2bf,  g_n2bf);
    cudaGetSymbolAddress((void**)&wqkvt, g_wqkvt);
    cudaGetSymbolAddress((void**)&w1t,   g_w1t);
    cudaGetSymbolAddress((void**)&bqkv,  g_bqkv);
    cudaGetSymbolAddress((void**)&qkv,   g_qkv);
    cudaGetSymbolAddress((void**)&vbf,   g_vbf);
    cudaGetSymbolAddress((void**)&ctx,   g_ctx);
    cudaGetSymbolAddress((void**)&bits,  g_bits);

    cudaFuncSetAttribute(attn_tc, cudaFuncAttributeMaxDynamicSharedMemorySize, ATT_SMEM);

    transpose_all<<<dim3(112, 16), dim3(32, 8)>>>(wq, wk, wv, w1, wqkvt, w1t);
    combine_bias<<<6, 256>>>(bq, bk, bv, bqkv);

    // 1) LN1 -> bf16
    ln_kernel<<<ROWS, 128>>>(x, gm1, be1, n1bf);

    // 2) fused QKV projection (HMMA): q,k tf32-fp32 -> qkv ; v bf16 -> vbf
    hmma_gemm<0><<<dim3(QKVN/128, ROWS/128), 256>>>(n1bf, wqkvt, bqkv, qkv, nullptr, QKVN,
                                                    nullptr, nullptr, nullptr, nullptr, vbf);

    // 3) tensor-core flash attention (round-4 online-softmax structure)
    attn_tc<<<dim3(SEQ/64, BHN), 128, ATT_SMEM>>>(qkv, vbf, ctx);

    // 4) x1 = x + att_out -> out ; n2 = LN(x1) -> bf16
    add_ln_kernel<<<ROWS, 128>>>(x, ctx, gm2, be2, out, n2bf);

    // 5) FFN1 (HMMA) -> spike bitmask (borderline exact-reverified from x1)
    hmma_gemm<1><<<dim3(FF/128, ROWS/128), 256>>>(n2bf, w1t, b1, nullptr, bits, 0,
                                                  out, gm2, be2, w1, nullptr);

    // 6) out = x1 + b2 + spikes @ w2 (sparse)
    ffn2_sparse<<<ROWS, 128>>>(bits, w2, b2, out);
}

// round 16
// speedup vs baseline: 1.1648x; 1.1648x over previous
#include <cuda_runtime.h>
#include <cuda_bf16.h>
#include <cuda_fp16.h>
#include <cstdint>

// ---------------- problem constants ----------------
#define MB   4
#define SEQ  2048
#define EMB  512
#define NH   8
#define HD   64
#define FF   2048
#define ROWS (MB*SEQ)     // 8192
#define BHN  (MB*NH)      // 32
#define QKVN (3*EMB)      // 1536

// ---------------- scratch (device globals) ----------------
__device__ __nv_bfloat16 g_n1bf[(size_t)ROWS*EMB];
__device__ __nv_bfloat16 g_n2bf[(size_t)ROWS*EMB];
__device__ __nv_bfloat16 g_wqkvt[(size_t)QKVN*EMB];   // [N=1536, K=512] bf16
__device__ __nv_bfloat16 g_w1t[(size_t)FF*EMB];       // [N=2048, K=512] bf16
__device__ float    g_bqkv[QKVN];
__device__ __half   g_qkvh[(size_t)3*BHN*SEQ*HD];     // fp16 q|k|v, [region][bh][seq][64]
__device__ float    g_ctx[(size_t)ROWS*EMB];
__device__ uint32_t g_bits[(size_t)ROWS*(FF/32)];

// ---------------- helpers ----------------
static __device__ __forceinline__ uint32_t s2u(const void* p) {
    uint32_t a;
    asm("{ .reg .u64 t; cvta.to.shared.u64 t, %1; cvt.u32.u64 %0, t; }" : "=r"(a) : "l"(p));
    return a;
}
static __device__ __forceinline__ void cp16(uint32_t s, const void* g) {
    asm volatile("cp.async.ca.shared.global [%0], [%1], 16;"
                 :: "r"(s), "l"(__cvta_generic_to_global(g)) : "memory");
}
static __device__ __forceinline__ void ldm_x4(uint32_t addr, uint32_t& r0, uint32_t& r1,
                                              uint32_t& r2, uint32_t& r3) {
    asm volatile("ldmatrix.sync.aligned.m8n8.x4.shared.b16 {%0,%1,%2,%3}, [%4];"
                 : "=r"(r0), "=r"(r1), "=r"(r2), "=r"(r3) : "r"(addr));
}
static __device__ __forceinline__ void ldm_x4t(uint32_t addr, uint32_t& r0, uint32_t& r1,
                                               uint32_t& r2, uint32_t& r3) {
    asm volatile("ldmatrix.sync.aligned.m8n8.x4.trans.shared.b16 {%0,%1,%2,%3}, [%4];"
                 : "=r"(r0), "=r"(r1), "=r"(r2), "=r"(r3) : "r"(addr));
}
// bf16 mma (GEMM path)
static __device__ __forceinline__ void mma16816(float* d, const uint32_t* a,
                                                uint32_t b0, uint32_t b1) {
    asm volatile("mma.sync.aligned.m16n8k16.row.col.f32.bf16.bf16.f32 "
                 "{%0,%1,%2,%3}, {%4,%5,%6,%7}, {%8,%9}, {%0,%1,%2,%3};"
                 : "+f"(d[0]), "+f"(d[1]), "+f"(d[2]), "+f"(d[3])
                 : "r"(a[0]), "r"(a[1]), "r"(a[2]), "r"(a[3]), "r"(b0), "r"(b1));
}
// fp16 mma (attention path)
static __device__ __forceinline__ void mma16816h(float* d, const uint32_t* a,
                                                 uint32_t b0, uint32_t b1) {
    asm volatile("mma.sync.aligned.m16n8k16.row.col.f32.f16.f16.f32 "
                 "{%0,%1,%2,%3}, {%4,%5,%6,%7}, {%8,%9}, {%0,%1,%2,%3};"
                 : "+f"(d[0]), "+f"(d[1]), "+f"(d[2]), "+f"(d[3])
                 : "r"(a[0]), "r"(a[1]), "r"(a[2]), "r"(a[3]), "r"(b0), "r"(b1));
}
static __device__ __forceinline__ uint32_t packbf2(float x, float y) {
    __nv_bfloat162 h = __floats2bfloat162_rn(x, y);
    return *(uint32_t*)&h;
}
static __device__ __forceinline__ uint32_t packh2(float x, float y) {
    __half2 h = __floats2half2_rn(x, y);
    return *(uint32_t*)&h;
}

// ---------------- block reduce (128 threads) ----------------
__device__ __forceinline__ void blockReduce2_128(float &a, float &b) {
    #pragma unroll
    for (int off = 16; off; off >>= 1) {
        a += __shfl_xor_sync(0xffffffffu, a, off);
        b += __shfl_xor_sync(0xffffffffu, b, off);
    }
    __shared__ float sa[4], sb[4];
    int w = threadIdx.x >> 5, ln = threadIdx.x & 31;
    if (ln == 0) { sa[w] = a; sb[w] = b; }
    __syncthreads();
    a = sa[0] + sa[1] + sa[2] + sa[3];
    b = sb[0] + sb[1] + sb[2] + sb[3];
}

static __device__ __forceinline__ void st_bf4(__nv_bfloat16* p, float4 o) {
    __nv_bfloat162 a = __floats2bfloat162_rn(o.x, o.y);
    __nv_bfloat162 b = __floats2bfloat162_rn(o.z, o.w);
    uint2 u;
    u.x = *(uint32_t*)&a;
    u.y = *(uint32_t*)&b;
    *(uint2*)p = u;
}

// ---------------- LN1 ----------------
__global__ void ln_kernel(const float* __restrict__ x,
                          const float* __restrict__ gam,
                          const float* __restrict__ bet,
                          __nv_bfloat16* __restrict__ out)
{
    int row = blockIdx.x;
    int t = threadIdx.x;
    float4 v = ((const float4*)(x + (size_t)row * EMB))[t];
    float s  = v.x + v.y + v.z + v.w;
    float ss = v.x*v.x + v.y*v.y + v.z*v.z + v.w*v.w;
    blockReduce2_128(s, ss);
    float mean = s * (1.0f / EMB);
    float var  = ss * (1.0f / EMB) - mean * mean;
    float r = rsqrtf(var + 1e-5f);
    float4 gv = ((const float4*)gam)[t];
    float4 bv = ((const float4*)bet)[t];
    float4 o;
    o.x = (v.x - mean) * r * gv.x + bv.x;
    o.y = (v.y - mean) * r * gv.y + bv.y;
    o.z = (v.z - mean) * r * gv.z + bv.z;
    o.w = (v.w - mean) * r * gv.w + bv.w;
    st_bf4(out + (size_t)row * EMB + t * 4, o);
}

// ---------------- residual add + LN2 ----------------
__global__ void add_ln_kernel(const float* __restrict__ x,
                              const float* __restrict__ ctx,
                              const float* __restrict__ gam,
                              const float* __restrict__ bet,
                              float* __restrict__ x1out,
                              __nv_bfloat16* __restrict__ nout)
{
    int row = blockIdx.x;
    int t = threadIdx.x;
    float4 xv = ((const float4*)(x   + (size_t)row * EMB))[t];
    float4 cv = ((const float4*)(ctx + (size_t)row * EMB))[t];
    float4 v;
    v.x = xv.x + cv.x; v.y = xv.y + cv.y; v.z = xv.z + cv.z; v.w = xv.w + cv.w;
    ((float4*)(x1out + (size_t)row * EMB))[t] = v;

    float s  = v.x + v.y + v.z + v.w;
    float ss = v.x*v.x + v.y*v.y + v.z*v.z + v.w*v.w;
    blockReduce2_128(s, ss);
    float mean = s * (1.0f / EMB);
    float var  = ss * (1.0f / EMB) - mean * mean;
    float r = rsqrtf(var + 1e-5f);
    float4 gv = ((const float4*)gam)[t];
    float4 bv = ((const float4*)bet)[t];
    float4 o;
    o.x = (v.x - mean) * r * gv.x + bv.x;
    o.y = (v.y - mean) * r * gv.y + bv.y;
    o.z = (v.z - mean) * r * gv.z + bv.z;
    o.w = (v.w - mean) * r * gv.w + bv.w;
    st_bf4(nout + (size_t)row * EMB + t * 4, o);
}

// ---------------- fused weight transposes: f32 [K,N] -> bf16 [N,K] ----------------
__global__ void transpose_all(const float* __restrict__ wq, const float* __restrict__ wk,
                              const float* __restrict__ wv, const float* __restrict__ w1,
                              __nv_bfloat16* __restrict__ wqkvt, __nv_bfloat16* __restrict__ w1t)
{
    __shared__ float tile[32][33];
    int bx = blockIdx.x;
    const float* in;
    __nv_bfloat16* out;
    int N, nb;
    if (bx < 48) {
        int mi = bx >> 4;
        in = (mi == 0) ? wq : ((mi == 1) ? wk : wv);
        out = wqkvt + (size_t)mi * 512 * EMB;
        N = 512;
        nb = (bx & 15) * 32;
    } else {
        in = w1; out = w1t; N = FF; nb = (bx - 48) * 32;
    }
    int kb = blockIdx.y * 32;
    int tx = threadIdx.x, ty = threadIdx.y;   // 32 x 8
    #pragma unroll
    for (int i = 0; i < 32; i += 8)
        tile[ty + i][tx] = in[(size_t)(kb + ty + i) * N + nb + tx];
    __syncthreads();
    #pragma unroll
    for (int i = 0; i < 32; i += 8)
        out[(size_t)(nb + ty + i) * EMB + kb + tx] = __float2bfloat16_rn(tile[tx][ty + i]);
}

__global__ void combine_bias(const float* __restrict__ bq, const float* __restrict__ bk,
                             const float* __restrict__ bv, float* __restrict__ o)
{
    int i = blockIdx.x * 256 + threadIdx.x;
    if (i < QKVN)
        o[i] = (i < 512) ? bq[i] : ((i < 1024) ? bk[i - 512] : bv[i - 1024]);
}

// exact fp32 recompute of h1[row][col] (rare borderline path)
static __device__ float exact_h1(const float* __restrict__ x1row,
                                 const float* __restrict__ g2,
                                 const float* __restrict__ be2,
                                 const float* __restrict__ w1f,
                                 int col, float bias0)
{
    float s = 0.f, ss = 0.f;
    for (int k = 0; k < EMB; ++k) { float v = x1row[k]; s += v; ss += v * v; }
    float mu = s * (1.0f / EMB);
    float var = ss * (1.0f / EMB) - mu * mu;
    float r = rsqrtf(var + 1e-5f);
    float d = bias0;
    for (int k = 0; k < EMB; ++k) {
        float nv = (x1row[k] - mu) * r * g2[k] + be2[k];
        d += nv * w1f[(size_t)k * FF + col];
    }
    return d;
}

// ---------------- HMMA bf16 GEMM ----------------
// EPI 0 (QKV): q,k,v all -> fp16 into qkvh [region][bh][seq][64]
// EPI 1 (FFN1): spike bitmask, borderline re-verified via exact fp32 LN+dot.
#define KCH 32
#define LDHW 40
#define STGH (128*LDHW)

template<int EPI>
__global__ void __launch_bounds__(256)
hmma_gemm(const __nv_bfloat16* __restrict__ A, const __nv_bfloat16* __restrict__ Bt,
          const float* __restrict__ bias, __half* __restrict__ qkvh,
          uint32_t* __restrict__ bits,
          const float* __restrict__ x1, const float* __restrict__ g2,
          const float* __restrict__ be2, const float* __restrict__ w1f)
{
    __shared__ __align__(16) __nv_bfloat16 sA[2][STGH];
    __shared__ __align__(16) __nv_bfloat16 sB[2][STGH];
    __shared__ float sBias[128];

    int t = threadIdx.x, lane = t & 31, warp = t >> 5;
    int wm = warp >> 2;
    int wn = warp & 3;
    int m0 = blockIdx.y * 128, n0 = blockIdx.x * 128;

    if (t < 128) sBias[t] = bias[n0 + t];

    uint32_t sAu = s2u(&sA[0][0]);
    uint32_t sBu = s2u(&sB[0][0]);
    int lr0 = t >> 2, lc = (t & 3) * 8;

    {
        #pragma unroll
        for (int it = 0; it < 2; ++it) {
            int r = lr0 + it * 64;
            uint32_t off = (uint32_t)(r * LDHW + lc) * 2;
            cp16(sAu + off, A  + (size_t)(m0 + r) * EMB + lc);
            cp16(sBu + off, Bt + (size_t)(n0 + r) * EMB + lc);
        }
        asm volatile("cp.async.commit_group;" ::: "memory");
    }

    float acc[4][4][4];
    #pragma unroll
    for (int i = 0; i < 4; i++)
        #pragma unroll
        for (int j = 0; j < 4; j++)
            #pragma unroll
            for (int f = 0; f < 4; f++) acc[i][j][f] = 0.f;

    const int NSTEP = EMB / KCH;
    #pragma unroll 1
    for (int s = 0; s < NSTEP; ++s) {
        if (s + 1 < NSTEP) {
            int stg = (s + 1) & 1;
            #pragma unroll
            for (int it = 0; it < 2; ++it) {
                int r = lr0 + it * 64;
                uint32_t off = (uint32_t)(stg * STGH + r * LDHW + lc) * 2;
                cp16(sAu + off, A  + (size_t)(m0 + r) * EMB + (s + 1) * KCH + lc);
                cp16(sBu + off, Bt + (size_t)(n0 + r) * EMB + (s + 1) * KCH + lc);
            }
            asm volatile("cp.async.commit_group;" ::: "memory");
            asm volatile("cp.async.wait_group 1;" ::: "memory");
        } else {
            asm volatile("cp.async.wait_group 0;" ::: "memory");
        }
        __syncthreads();

        int stg = s & 1;
        uint32_t aB = sAu + (uint32_t)(stg * STGH) * 2;
        uint32_t bB = sBu + (uint32_t)(stg * STGH) * 2;

        #pragma unroll
        for (int k16 = 0; k16 < 2; ++k16) {
            uint32_t a[4][4];
            #pragma unroll
            for (int mt = 0; mt < 4; ++mt) {
                int row = wm * 64 + mt * 16 + (lane & 15);
                int col = k16 * 16 + (lane >> 4) * 8;
                ldm_x4(aB + (uint32_t)(row * LDHW + col) * 2,
                       a[mt][0], a[mt][1], a[mt][2], a[mt][3]);
            }
            uint32_t b[2][4];
            #pragma unroll
            for (int nb = 0; nb < 2; ++nb) {
                int nrow = wn * 32 + nb * 16 + (lane & 7) + ((lane >> 4) & 1) * 8;
                int col  = k16 * 16 + ((lane >> 3) & 1) * 8;
                ldm_x4(bB + (uint32_t)(nrow * LDHW + col) * 2,
                       b[nb][0], b[nb][1], b[nb][2], b[nb][3]);
            }
            #pragma unroll
            for (int mt = 0; mt < 4; ++mt)
                #pragma unroll
                for (int nt = 0; nt < 4; ++nt)
                    mma16816(acc[mt][nt], a[mt],
                             b[nt >> 1][(nt & 1) * 2], b[nt >> 1][(nt & 1) * 2 + 1]);
        }
        __syncthreads();
    }

    int qr = lane >> 2;
    int qc = (lane & 3) * 2;
    if (EPI == 0) {
        #pragma unroll
        for (int mt = 0; mt < 4; ++mt) {
            int r0 = m0 + wm * 64 + mt * 16 + qr;
            int mi = r0 >> 11, s0 = r0 & (SEQ - 1), s1 = (r0 + 8) & (SEQ - 1);
            #pragma unroll
            for (int nt = 0; nt < 4; ++nt) {
                int cofs = wn * 32 + nt * 8 + qc;
                int col = n0 + cofs;
                float v00 = acc[mt][nt][0] + sBias[cofs];
                float v01 = acc[mt][nt][1] + sBias[cofs + 1];
                float v10 = acc[mt][nt][2] + sBias[cofs];
                float v11 = acc[mt][nt][3] + sBias[cofs + 1];
                int region = col >> 9;              // 0=q, 1=k, 2=v
                int hh = (col >> 6) & 7, dd = col & 63;
                size_t base = (((size_t)region * BHN + (size_t)mi * NH + hh) * SEQ);
                *(uint32_t*)(qkvh + (base + s0) * HD + dd) = packh2(v00, v01);
                *(uint32_t*)(qkvh + (base + s1) * HD + dd) = packh2(v10, v11);
            }
        }
    } else {
        #pragma unroll
        for (int mt = 0; mt < 4; ++mt) {
            int r0 = m0 + wm * 64 + mt * 16 + qr;
            uint32_t w0 = 0, w1m = 0;
            #pragma unroll
            for (int nt = 0; nt < 4; ++nt) {
                int cofs = wn * 32 + nt * 8 + qc;
                int col = n0 + cofs;
                #pragma unroll
                for (int e = 0; e < 2; ++e) {
                    int pos = nt * 8 + qc + e;
                    float b0 = sBias[cofs + e];
                    float va = acc[mt][nt][e] + b0;
                    float vb = acc[mt][nt][2 + e] + b0;
                    if (fabsf(va - 2.0f) < 0.02f)
                        va = exact_h1(x1 + (size_t)r0 * EMB, g2, be2, w1f, col + e, b0);
                    if (fabsf(vb - 2.0f) < 0.02f)
                        vb = exact_h1(x1 + (size_t)(r0 + 8) * EMB, g2, be2, w1f, col + e, b0);
                    if (va >= 2.0f) w0  |= (1u << pos);
                    if (vb >= 2.0f) w1m |= (1u << pos);
                }
            }
            w0  |= __shfl_xor_sync(0xffffffffu, w0, 1);
            w0  |= __shfl_xor_sync(0xffffffffu, w0, 2);
            w1m |= __shfl_xor_sync(0xffffffffu, w1m, 1);
            w1m |= __shfl_xor_sync(0xffffffffu, w1m, 2);
            if ((lane & 3) == 0) {
                int wcol = (n0 >> 5) + wn;
                bits[(size_t)r0 * (FF/32) + wcol]       = w0;
                bits[(size_t)(r0 + 8) * (FF/32) + wcol] = w1m;
            }
        }
    }
}

// ---------------- fp16 tensor-core flash attention ----------------
// CTA: 64 q rows of one (m,h); 4 warps x 16 rows; 64-key tiles double-buffered.
// QK^T fp16 m16n8k16 (ldmatrix A+B frags), online softmax fp32, P*V fp16.
// smem (fp16, 72-half rows = 144B): Q [64][72] | K [2][64][72] | V [2][64][72]
#define ASM_Q 0
#define ASM_K 9216
#define ASM_V 27648
#define KSTG 9216
#define ATT_SMEM 46080

__global__ void __launch_bounds__(128, 4)
attn_tc(const __half* __restrict__ qkvh, float* __restrict__ O)
{
    extern __shared__ __align__(16) char smx[];
    uint32_t smb = s2u(smx);

    int bh = blockIdx.y;
    int m = bh >> 3, h = bh & 7;
    int q0 = blockIdx.x * 64;
    int t = threadIdx.x, lane = t & 31, warp = t >> 5;
    int g = lane >> 2, tq = lane & 3;

    const __half* qg  = qkvh + ((size_t)bh * SEQ + q0) * HD;
    const __half* kg0 = qkvh + ((size_t)(BHN + bh) * SEQ) * HD;
    const __half* vg0 = qkvh + ((size_t)(2 * BHN + bh) * SEQ) * HD;

    // prefetch: K0 + V0, then Q
    {
        #pragma unroll
        for (int i = 0; i < 4; ++i) {
            int idx = t + i * 128;
            int r = idx >> 3, c = idx & 7;
            cp16(smb + ASM_K + r * 144 + c * 16, kg0 + (size_t)r * HD + c * 8);
            cp16(smb + ASM_V + r * 144 + c * 16, vg0 + (size_t)r * HD + c * 8);
        }
        asm volatile("cp.async.commit_group;" ::: "memory");
        #pragma unroll
        for (int i = 0; i < 4; ++i) {
            int idx = t + i * 128;
            int r = idx >> 3, c = idx & 7;
            cp16(smb + ASM_Q + r * 144 + c * 16, qg + (size_t)r * HD + c * 8);
        }
        asm volatile("cp.async.commit_group;" ::: "memory");
        asm volatile("cp.async.wait_group 0;" ::: "memory");
    }
    __syncthreads();

    // Q A-fragments: 4 ldmatrix.x4 (one per k16), register-resident for all tiles
    uint32_t qf[4][4];
    {
        int qrow = warp * 16 + (lane & 15);
        #pragma unroll
        for (int k16 = 0; k16 < 4; ++k16) {
            uint32_t addr = smb + ASM_Q
                          + (uint32_t)(qrow * 72 + k16 * 16 + 8 * (lane >> 4)) * 2;
            ldm_x4(addr, qf[k16][0], qf[k16][1], qf[k16][2], qf[k16][3]);
        }
    }

    float mrow[2] = {-1e30f, -1e30f}, lrow[2] = {0.f, 0.f};
    float accO[8][4];
    #pragma unroll
    for (int j = 0; j < 8; ++j)
        #pragma unroll
        for (int e = 0; e < 4; ++e) accO[j][e] = 0.f;

    #pragma unroll 1
    for (int kt = 0; kt < SEQ / 64; ++kt) {
        __syncthreads();   // all warps done with the stage about to be overwritten
        if (kt + 1 < SEQ / 64) {
            int st = (kt + 1) & 1;
            const __half* kg = kg0 + (size_t)(kt + 1) * 64 * HD;
            const __half* vg = vg0 + (size_t)(kt + 1) * 64 * HD;
            #pragma unroll
            for (int i = 0; i < 4; ++i) {
                int idx = t + i * 128;
                int r = idx >> 3, c = idx & 7;
                cp16(smb + ASM_K + st * KSTG + r * 144 + c * 16, kg + (size_t)r * HD + c * 8);
                cp16(smb + ASM_V + st * KSTG + r * 144 + c * 16, vg + (size_t)r * HD + c * 8);
            }
            asm volatile("cp.async.commit_group;" ::: "memory");
            asm volatile("cp.async.wait_group 1;" ::: "memory");
        } else {
            asm volatile("cp.async.wait_group 0;" ::: "memory");
        }
        __syncthreads();

        int st = kt & 1;
        uint32_t kB = smb + ASM_K + st * KSTG;

        // ---- S = Q K^T (fp16 m16n8k16, B-frags via ldmatrix) ----
        float accS[8][4];
        #pragma unroll
        for (int j = 0; j < 8; ++j)
            #pragma unroll
            for (int e = 0; e < 4; ++e) accS[j][e] = 0.f;

        int brow = (lane & 7) + 8 * ((lane >> 4) & 1);
        int bcol = 8 * ((lane >> 3) & 1);
        #pragma unroll
        for (int k16 = 0; k16 < 4; ++k16) {
            #pragma unroll
            for (int n16 = 0; n16 < 4; ++n16) {
                uint32_t b0, b1, b2, b3;
                uint32_t addr = kB + (uint32_t)((n16 * 16 + brow) * 72
                              + k16 * 16 + bcol) * 2;
                ldm_x4(addr, b0, b1, b2, b3);
                mma16816h(accS[n16 * 2],     qf[k16], b0, b1);
                mma16816h(accS[n16 * 2 + 1], qf[k16], b2, b3);
            }
        }

        // ---- online softmax (rows g, g+8 of this warp's 16) ----
        float mx0 = -1e30f, mx1 = -1e30f;
        #pragma unroll
        for (int j = 0; j < 8; ++j) {
            mx0 = fmaxf(mx0, fmaxf(accS[j][0], accS[j][1]));
            mx1 = fmaxf(mx1, fmaxf(accS[j][2], accS[j][3]));
        }
        mx0 = fmaxf(mx0, __shfl_xor_sync(0xffffffffu, mx0, 1));
        mx0 = fmaxf(mx0, __shfl_xor_sync(0xffffffffu, mx0, 2));
        mx1 = fmaxf(mx1, __shfl_xor_sync(0xffffffffu, mx1, 1));
        mx1 = fmaxf(mx1, __shfl_xor_sync(0xffffffffu, mx1, 2));
        float mn0 = fmaxf(mrow[0], mx0), mn1 = fmaxf(mrow[1], mx1);
        float sc0 = __expf(mrow[0] - mn0), sc1 = __expf(mrow[1] - mn1);
        float sum0 = 0.f, sum1 = 0.f;
        #pragma unroll
        for (int j = 0; j < 8; ++j) {
            accS[j][0] = __expf(accS[j][0] - mn0);
            accS[j][1] = __expf(accS[j][1] - mn0);
            accS[j][2] = __expf(accS[j][2] - mn1);
            accS[j][3] = __expf(accS[j][3] - mn1);
            sum0 += accS[j][0] + accS[j][1];
            sum1 += accS[j][2] + accS[j][3];
        }
        sum0 += __shfl_xor_sync(0xffffffffu, sum0, 1);
        sum0 += __shfl_xor_sync(0xffffffffu, sum0, 2);
        sum1 += __shfl_xor_sync(0xffffffffu, sum1, 1);
        sum1 += __shfl_xor_sync(0xffffffffu, sum1, 2);
        lrow[0] = lrow[0] * sc0 + sum0;
        lrow[1] = lrow[1] * sc1 + sum1;
        mrow[0] = mn0; mrow[1] = mn1;
        #pragma unroll
        for (int j = 0; j < 8; ++j) {
            accO[j][0] *= sc0; accO[j][1] *= sc0;
            accO[j][2] *= sc1; accO[j][3] *= sc1;
        }

        // ---- O += P V (fp16); P fragments come straight from accS ----
        uint32_t vB = smb + ASM_V + st * KSTG;
        #pragma unroll
        for (int sk = 0; sk < 4; ++sk) {
            uint32_t pa[4];
            pa[0] = packh2(accS[2 * sk][0],     accS[2 * sk][1]);
            pa[1] = packh2(accS[2 * sk][2],     accS[2 * sk][3]);
            pa[2] = packh2(accS[2 * sk + 1][0], accS[2 * sk + 1][1]);
            pa[3] = packh2(accS[2 * sk + 1][2], accS[2 * sk + 1][3]);
            #pragma unroll
            for (int dj = 0; dj < 4; ++dj) {
                uint32_t v0, v1, v2, v3;
                uint32_t addr = vB + (uint32_t)((sk * 16 + (lane & 15)) * 72
                              + dj * 16 + 8 * (lane >> 4)) * 2;
                ldm_x4t(addr, v0, v1, v2, v3);
                mma16816h(accO[2 * dj],     pa, v0, v1);
                mma16816h(accO[2 * dj + 1], pa, v2, v3);
            }
        }
    }

    // ---- epilogue ----
    float inv0 = 1.0f / lrow[0];
    float inv1 = 1.0f / lrow[1];
    int qrow = warp * 16 + g;
    float* ob = O + ((size_t)(m * SEQ + q0 + qrow)) * EMB + h * 64;
    #pragma unroll
    for (int j = 0; j < 8; ++j) {
        float2 a2, b2;
        a2.x = accO[j][0] * inv0; a2.y = accO[j][1] * inv0;
        b2.x = accO[j][2] * inv1; b2.y = accO[j][3] * inv1;
        *(float2*)(ob + j * 8 + 2 * tq) = a2;
        *(float2*)(ob + (size_t)8 * EMB + j * 8 + 2 * tq) = b2;
    }
}

// ---------------- sparse FFN2 ----------------
__global__ void __launch_bounds__(128)
ffn2_sparse(const uint32_t* __restrict__ bits, const float* __restrict__ w2,
            const float* __restrict__ b2, float* __restrict__ out)
{
    int row = blockIdx.x, t = threadIdx.x;
    __shared__ uint32_t sm[FF/32];
    if (t < FF/32) sm[t] = bits[(size_t)row * (FF/32) + t];
    __syncthreads();
    float4 acc = *(const float4*)(b2 + t * 4);
    #pragma unroll 4
    for (int w = 0; w < FF/32; ++w) {
        uint32_t m = sm[w];
        while (m) {
            int j = __ffs((int)m) - 1;
            m &= m - 1;
            int col = w * 32 + j;
            float4 wv = *(const float4*)(w2 + (size_t)col * EMB + t * 4);
            acc.x += wv.x; acc.y += wv.y; acc.z += wv.z; acc.w += wv.w;
        }
    }
    float4 cur = *(const float4*)(out + (size_t)row * EMB + t * 4);
    cur.x += acc.x; cur.y += acc.y; cur.z += acc.z; cur.w += acc.w;
    *(float4*)(out + (size_t)row * EMB + t * 4) = cur;
}

// ---------------- launch ----------------
extern "C" void kernel_launch(void* const* d_in, const int* in_sizes, int n_in,
                              void* d_out, int out_size)
{
    const float* x   = (const float*)d_in[0];
    const float* wq  = (const float*)d_in[1];
    const float* bq  = (const float*)d_in[2];
    const float* wk  = (const float*)d_in[3];
    const float* bk  = (const float*)d_in[4];
    const float* wv  = (const float*)d_in[5];
    const float* bv  = (const float*)d_in[6];
    const float* w1  = (const float*)d_in[7];
    const float* b1  = (const float*)d_in[8];
    const float* w2  = (const float*)d_in[9];
    const float* b2  = (const float*)d_in[10];
    const float* gm1 = (const float*)d_in[11];
    const float* be1 = (const float*)d_in[12];
    const float* gm2 = (const float*)d_in[13];
    const float* be2 = (const float*)d_in[14];
    float* out = (float*)d_out;

    __nv_bfloat16 *n1bf, *n2bf, *wqkvt, *w1t;
    __half *qkvh;
    float *bqkv, *ctx;
    uint32_t *bits;
    cudaGetSymbolAddress((void**)&n1bf,  g_n1bf);
    cudaGetSymbolAddress((void**)&n2bf,  g_n2bf);
    cudaGetSymbolAddress((void**)&wqkvt, g_wqkvt);
    cudaGetSymbolAddress((void**)&w1t,   g_w1t);
    cudaGetSymbolAddress((void**)&bqkv,  g_bqkv);
    cudaGetSymbolAddress((void**)&qkvh,  g_qkvh);
    cudaGetSymbolAddress((void**)&ctx,   g_ctx);
    cudaGetSymbolAddress((void**)&bits,  g_bits);

    cudaFuncSetAttribute(attn_tc, cudaFuncAttributeMaxDynamicSharedMemorySize, ATT_SMEM);

    transpose_all<<<dim3(112, 16), dim3(32, 8)>>>(wq, wk, wv, w1, wqkvt, w1t);
    combine_bias<<<6, 256>>>(bq, bk, bv, bqkv);

    // 1) LN1 -> bf16
    ln_kernel<<<ROWS, 128>>>(x, gm1, be1, n1bf);

    // 2) fused QKV projection (HMMA): q,k,v -> fp16 packed [region][bh][seq][64]
    hmma_gemm<0><<<dim3(QKVN/128, ROWS/128), 256>>>(n1bf, wqkvt, bqkv, qkvh, nullptr,
                                                    nullptr, nullptr, nullptr, nullptr);

    // 3) fp16 tensor-core flash attention
    attn_tc<<<dim3(SEQ/64, BHN), 128, ATT_SMEM>>>(qkvh, ctx);

    // 4) x1 = x + att_out -> out ; n2 = LN(x1) -> bf16
    add_ln_kernel<<<ROWS, 128>>>(x, ctx, gm2, be2, out, n2bf);

    // 5) FFN1 (HMMA) -> spike bitmask (borderline exact-reverified from x1)
    hmma_gemm<1><<<dim3(FF/128, ROWS/128), 256>>>(n2bf, w1t, b1, nullptr, bits,
                                                  out, gm2, be2, w1);

    // 6) out = x1 + b2 + spikes @ w2 (sparse)
    ffn2_sparse<<<ROWS, 128>>>(bits, w2, b2, out);
}